// round 14
// baseline (speedup 1.0000x reference)
#include <cuda_runtime.h>
#include <cuda_bf16.h>
#include <math.h>
#include <stdint.h>

#define NROW 12288
#define DIM  512
#define FEAT 128
#define TR   32            // rows per scan tile
#define NBR  384           // NROW / TR
#define SA   72            // padded bf16 row stride in smem (conflict-free)
#define NBUK 4096
#define ABUF (64 * SA)     // ushorts per A array
#define BBUF (128 * SA)    // ushorts per B array
#define GEMM_BLOCKS 192
#define SORT_BLOCKS 48

// ---------------- scratch (device globals; allocations forbidden) -----------
__device__ float g_scale[FEAT];
__device__ unsigned short g_vhi[FEAT * DIM];
__device__ unsigned short g_vlo[FEAT * DIM];
__device__ float g_ppart[4 * DIM * 2];        // per-prep-block partial p
__device__ float g_z[NROW * FEAT];
__device__ float g_s[NROW];
__device__ float g_d[NROW];
__device__ unsigned long long g_dkey[NROW];
__device__ int   g_hist[NBUK];
__device__ int   g_hstart[NBUK];
__device__ unsigned long long g_bkeys[NROW];
__device__ unsigned int g_kmin, g_kmax;
__device__ int   g_inv[NROW];
__device__ float g_sortedD[NROW];
__device__ float g_expD[NROW];
__device__ float g_S0[(NROW + 1) * FEAT];
__device__ float g_SufE[(NROW + 1) * FEAT];
__device__ float g_c1[NROW + 1];
__device__ float g_T0[NBR * FEAT];
__device__ float g_TS[NBR * FEAT];
__device__ float g_Tc[NBR];
__device__ float g_off0[(NBR + 1) * FEAT];
__device__ float g_offS[(NBR + 1) * FEAT];
__device__ float g_offc[NBR + 1];
__device__ int   g_cnt1, g_gen1;   // sort-branch barrier
__device__ int   g_cnt2, g_gen2;   // scan-kernel barrier

// ---------------- helpers -----------------------------------------------------
__device__ __forceinline__ void grid_barrier(int expected, int* cnt, int* gen) {
    __syncthreads();
    if (threadIdx.x == 0) {
        int g0 = *((volatile int*)gen);
        __threadfence();
        if (atomicAdd(cnt, 1) == expected - 1) {
            *((volatile int*)cnt) = 0;
            __threadfence();
            atomicAdd(gen, 1);
        } else {
            while (*((volatile int*)gen) == g0) { __nanosleep(64); }
            __threadfence();
        }
    }
    __syncthreads();
}
__device__ __forceinline__ unsigned int float_key(float x) {
    unsigned int u = __float_as_uint(x);
    return (u & 0x80000000u) ? ~u : (u | 0x80000000u);
}
__device__ __forceinline__ uint32_t smem_u32(const void* p) {
    uint32_t a;
    asm("{ .reg .u64 t; cvta.to.shared.u64 t, %1; cvt.u32.u64 %0, t; }" : "=r"(a) : "l"(p));
    return a;
}
__device__ __forceinline__ void mma_bf16(float* c, const uint32_t* a,
                                         uint32_t b0, uint32_t b1) {
    asm volatile(
        "mma.sync.aligned.m16n8k16.row.col.f32.bf16.bf16.f32 "
        "{%0,%1,%2,%3}, {%4,%5,%6,%7}, {%8,%9}, {%0,%1,%2,%3};"
        : "+f"(c[0]), "+f"(c[1]), "+f"(c[2]), "+f"(c[3])
        : "r"(a[0]), "r"(a[1]), "r"(a[2]), "r"(a[3]), "r"(b0), "r"(b1));
}
#define LDSM4(r, addr) \
    asm volatile("ldmatrix.sync.aligned.m8n8.x4.shared.b16 {%0,%1,%2,%3}, [%4];" \
        : "=r"((r)[0]), "=r"((r)[1]), "=r"((r)[2]), "=r"((r)[3]) : "r"(addr))
__device__ __forceinline__ void cp16(uint32_t s, const void* g) {
    asm volatile("cp.async.cg.shared.global [%0], [%1], 16;" :: "r"(s), "l"(g));
}
__device__ __forceinline__ uint32_t pack_hi(float a, float b) {
    __nv_bfloat16 h0 = __float2bfloat16(a);
    __nv_bfloat16 h1 = __float2bfloat16(b);
    return ((uint32_t)__bfloat16_as_ushort(h1) << 16) | __bfloat16_as_ushort(h0);
}

// ---------------- 1) prep: scale + v split + p partials + hist zero ----------
__global__ void __launch_bounds__(1024) prep_kernel(const float* __restrict__ v,
                                                    const float* __restrict__ g,
                                                    const float* __restrict__ att) {
    __shared__ float sp[DIM * 2];   // 4KB partial p for this block's 32 features
    const int tid  = threadIdx.x;
    const int gtid = blockIdx.x * 1024 + tid;      // 0..4095
    g_hist[gtid] = 0;
    if (gtid == 0) { g_kmin = 0xFFFFFFFFu; g_kmax = 0u; }
    sp[tid] = 0.f;

    const int wid  = tid >> 5;
    const int lane = tid & 31;
    const int f    = blockIdx.x * 32 + wid;

    const float* vr = v + (size_t)f * DIM + lane * 16;
    float4 a0 = *(const float4*)(vr);
    float4 a1 = *(const float4*)(vr + 4);
    float4 a2 = *(const float4*)(vr + 8);
    float4 a3 = *(const float4*)(vr + 12);

    float ss = a0.x * a0.x + a0.y * a0.y + a0.z * a0.z + a0.w * a0.w
             + a1.x * a1.x + a1.y * a1.y + a1.z * a1.z + a1.w * a1.w
             + a2.x * a2.x + a2.y * a2.y + a2.z * a2.z + a2.w * a2.w
             + a3.x * a3.x + a3.y * a3.y + a3.z * a3.z + a3.w * a3.w;
#pragma unroll
    for (int off = 16; off; off >>= 1) ss += __shfl_xor_sync(0xffffffffu, ss, off);
    float sc = g[f] / sqrtf(ss);
    if (lane == 0) g_scale[f] = sc;

    const float as = att[f];
    const float ad = att[FEAT + f];
    __syncthreads();   // sp zero visible

    float vals[16] = {a0.x, a0.y, a0.z, a0.w, a1.x, a1.y, a1.z, a1.w,
                      a2.x, a2.y, a2.z, a2.w, a3.x, a3.y, a3.z, a3.w};
    uint32_t hi[8], lo[8];
#pragma unroll
    for (int q = 0; q < 8; q++) {
        float x0 = vals[2 * q] * sc;
        float x1 = vals[2 * q + 1] * sc;
        int k0 = lane * 16 + 2 * q;
        atomicAdd(&sp[k0 * 2 + 0], x0 * as);
        atomicAdd(&sp[k0 * 2 + 1], x0 * ad);
        atomicAdd(&sp[(k0 + 1) * 2 + 0], x1 * as);
        atomicAdd(&sp[(k0 + 1) * 2 + 1], x1 * ad);
        __nv_bfloat16 h0 = __float2bfloat16(x0);
        __nv_bfloat16 h1 = __float2bfloat16(x1);
        hi[q] = ((uint32_t)__bfloat16_as_ushort(h1) << 16) | __bfloat16_as_ushort(h0);
        lo[q] = pack_hi(x0 - __bfloat162float(h0), x1 - __bfloat162float(h1));
    }
    uint4* dh = (uint4*)(g_vhi + (size_t)f * DIM + lane * 16);
    uint4* dl = (uint4*)(g_vlo + (size_t)f * DIM + lane * 16);
    dh[0] = make_uint4(hi[0], hi[1], hi[2], hi[3]);
    dh[1] = make_uint4(hi[4], hi[5], hi[6], hi[7]);
    dl[0] = make_uint4(lo[0], lo[1], lo[2], lo[3]);
    dl[1] = make_uint4(lo[4], lo[5], lo[6], lo[7]);
    __syncthreads();
    g_ppart[blockIdx.x * (DIM * 2) + tid] = sp[tid];
}

// ---------------- 2) FUSED: gemm blocks [0,192) + sd/sort blocks [192,240) ---
__global__ void __launch_bounds__(256, 2) fused_kernel(const float* __restrict__ x,
                                                       const float* __restrict__ b,
                                                       const float* __restrict__ att) {
    extern __shared__ unsigned short sm[];
    const int tid = threadIdx.x;
    const int bid = blockIdx.x;

    if (bid < GEMM_BLOCKS) {
        // ================= GEMM branch =================
        unsigned short* aH = sm;
        unsigned short* aL = sm + ABUF;
        unsigned short* bB = sm + 2 * ABUF;

        const int w    = tid >> 5;
        const int lane = tid & 31;
        const int g    = lane >> 2;
        const int tig  = lane & 3;
        const int mw   = w & 1;
        const int nw   = w >> 1;
        const int bm   = bid * 64;
        const int rb   = mw * 32;
        const int n0   = nw * 32;

        const uint32_t aHs = smem_u32(aH), aLs = smem_u32(aL);
        const uint32_t bBs = smem_u32(bB);
        const uint32_t BOFF = 2 * BBUF * 2;

        const int rA = (lane & 7) + ((lane >> 3) & 1) * 8;
        const int cA = (lane >> 4) * 8;
        uint32_t aAdH[2], aAdL[2];
#pragma unroll
        for (int mi = 0; mi < 2; mi++) {
            aAdH[mi] = aHs + ((rb + mi * 16 + rA) * SA + cA) * 2;
            aAdL[mi] = aLs + ((rb + mi * 16 + rA) * SA + cA) * 2;
        }
        const int rB = (lane & 7) + (lane >> 4) * 8;
        const int cB = ((lane >> 3) & 1) * 8;
        uint32_t bAdH[2], bAdL[2];
#pragma unroll
        for (int j = 0; j < 2; j++) {
            bAdH[j] = bBs + ((n0 + j * 16 + rB) * SA + cB) * 2;
            bAdL[j] = bBs + BBUF * 2 + ((n0 + j * 16 + rB) * SA + cB) * 2;
        }

        const int brr = tid >> 3;
        const int bu  = tid & 7;

        float acc[2][4][4];
#pragma unroll
        for (int mi = 0; mi < 2; mi++)
#pragma unroll
            for (int nt = 0; nt < 4; nt++)
#pragma unroll
                for (int q = 0; q < 4; q++) acc[mi][nt][q] = 0.f;

#pragma unroll
        for (int p = 0; p < 4; p++) {
            int r = p * 32 + brr;
            size_t gv = (size_t)r * DIM + bu * 8;
            uint32_t so = (uint32_t)(r * SA + bu * 8) * 2;
            cp16(bBs + so, g_vhi + gv);
            cp16(bBs + BBUF * 2 + so, g_vlo + gv);
        }
        asm volatile("cp.async.commit_group;" ::: "memory");

        float4 xr[4];
#pragma unroll
        for (int p = 0; p < 4; p++) {
            int li = tid + p * 256;
            int r  = li >> 4;
            int c4 = (li & 15) * 4;
            xr[p] = *(const float4*)(x + (size_t)(bm + r) * DIM + c4);
        }

        for (int c = 0; c < 8; c++) {
            const uint32_t boff = (uint32_t)(c & 1) * BOFF;
#pragma unroll
            for (int p = 0; p < 4; p++) {
                int li = tid + p * 256;
                int r  = li >> 4;
                int c4 = (li & 15) * 4;
                float4 xv = xr[p];
                __nv_bfloat16 h0 = __float2bfloat16(xv.x);
                __nv_bfloat16 h1 = __float2bfloat16(xv.y);
                __nv_bfloat16 h2 = __float2bfloat16(xv.z);
                __nv_bfloat16 h3 = __float2bfloat16(xv.w);
                uint2 hv, lv;
                hv.x = ((uint32_t)__bfloat16_as_ushort(h1) << 16) | __bfloat16_as_ushort(h0);
                hv.y = ((uint32_t)__bfloat16_as_ushort(h3) << 16) | __bfloat16_as_ushort(h2);
                lv.x = pack_hi(xv.x - __bfloat162float(h0), xv.y - __bfloat162float(h1));
                lv.y = pack_hi(xv.z - __bfloat162float(h2), xv.w - __bfloat162float(h3));
                *(uint2*)&aH[r * SA + c4] = hv;
                *(uint2*)&aL[r * SA + c4] = lv;
            }
            if (c < 7) {
                const int k0n = (c + 1) * 64;
                const uint32_t bo2 = (uint32_t)((c + 1) & 1) * BOFF;
#pragma unroll
                for (int p = 0; p < 4; p++) {
                    int r = p * 32 + brr;
                    size_t gv = (size_t)r * DIM + k0n + bu * 8;
                    uint32_t so = (uint32_t)(r * SA + bu * 8) * 2;
                    cp16(bBs + bo2 + so, g_vhi + gv);
                    cp16(bBs + bo2 + BBUF * 2 + so, g_vlo + gv);
                }
                asm volatile("cp.async.commit_group;" ::: "memory");
                asm volatile("cp.async.wait_group 1;" ::: "memory");
            } else {
                asm volatile("cp.async.wait_group 0;" ::: "memory");
            }
            __syncthreads();

            if (c < 7) {
                const int k0n = (c + 1) * 64;
#pragma unroll
                for (int p = 0; p < 4; p++) {
                    int li = tid + p * 256;
                    int r  = li >> 4;
                    int c4 = (li & 15) * 4;
                    xr[p] = *(const float4*)(x + (size_t)(bm + r) * DIM + k0n + c4);
                }
            }

#pragma unroll
            for (int kt = 0; kt < 4; kt++) {
                uint32_t ah[2][4], al[2][4];
                LDSM4(ah[0], aAdH[0] + kt * 32);
                LDSM4(ah[1], aAdH[1] + kt * 32);
                LDSM4(al[0], aAdL[0] + kt * 32);
                LDSM4(al[1], aAdL[1] + kt * 32);
#pragma unroll
                for (int j = 0; j < 2; j++) {
                    uint32_t bh[4], bl[4];
                    LDSM4(bh, bAdH[j] + boff + kt * 32);
                    LDSM4(bl, bAdL[j] + boff + kt * 32);
#pragma unroll
                    for (int mi = 0; mi < 2; mi++) {
                        mma_bf16(acc[mi][2 * j],     ah[mi], bh[0], bh[1]);
                        mma_bf16(acc[mi][2 * j],     ah[mi], bl[0], bl[1]);
                        mma_bf16(acc[mi][2 * j],     al[mi], bh[0], bh[1]);
                        mma_bf16(acc[mi][2 * j + 1], ah[mi], bh[2], bh[3]);
                        mma_bf16(acc[mi][2 * j + 1], ah[mi], bl[2], bl[3]);
                        mma_bf16(acc[mi][2 * j + 1], al[mi], bh[2], bh[3]);
                    }
                }
            }
            __syncthreads();
        }

        // epilogue: z = acc + b (store only)
#pragma unroll
        for (int mi = 0; mi < 2; mi++) {
            const int row0 = bm + rb + mi * 16 + g;
#pragma unroll
            for (int nt = 0; nt < 4; nt++) {
                int cb = n0 + nt * 8 + tig * 2;
                float2 bb = *(const float2*)&b[cb];
                *(float2*)&g_z[(size_t)row0 * FEAT + cb] =
                    make_float2(acc[mi][nt][0] + bb.x, acc[mi][nt][1] + bb.y);
                *(float2*)&g_z[(size_t)(row0 + 8) * FEAT + cb] =
                    make_float2(acc[mi][nt][2] + bb.x, acc[mi][nt][3] + bb.y);
            }
        }
    } else {
        // ================= sd + sort branch (48 blocks) =================
        const int sbid = bid - GEMM_BLOCKS;
        const int lane = tid & 31;
        const int wid  = tid >> 5;
        float* ps = (float*)sm;            // [512]
        float* pd = ps + DIM;              // [512]

        // assemble p from 4 prep partials
        for (int q = tid; q < DIM; q += 256) {
            float accs = 0.f, accd = 0.f;
#pragma unroll
            for (int part = 0; part < 4; part++) {
                accs += g_ppart[part * (DIM * 2) + q * 2 + 0];
                accd += g_ppart[part * (DIM * 2) + q * 2 + 1];
            }
            ps[q] = accs;
            pd[q] = accd;
        }
        // c_s = b.att_src, c_d = b.att_dst (per-warp)
        float cs = 0.f, cd = 0.f;
#pragma unroll
        for (int q = 0; q < 4; q++) {
            int f = lane + q * 32;
            float bf = b[f];
            cs += bf * att[f];
            cd += bf * att[FEAT + f];
        }
#pragma unroll
        for (int off = 16; off; off >>= 1) {
            cs += __shfl_xor_sync(0xffffffffu, cs, off);
            cd += __shfl_xor_sync(0xffffffffu, cd, off);
        }
        __syncthreads();

        // sd matvec: warp per row, 32 rows per warp
        unsigned int kmn = 0xFFFFFFFFu, kmx = 0u;
#pragma unroll 1
        for (int rr = 0; rr < 32; rr++) {
            int i = sbid * 256 + wid * 32 + rr;
            const float4* xr4 = (const float4*)(x + (size_t)i * DIM) + lane;
            float s = 0.f, d = 0.f;
#pragma unroll
            for (int q = 0; q < 4; q++) {
                float4 xv = xr4[q * 32];
                int k = (lane + q * 32) * 4;
                s += xv.x * ps[k] + xv.y * ps[k + 1] + xv.z * ps[k + 2] + xv.w * ps[k + 3];
                d += xv.x * pd[k] + xv.y * pd[k + 1] + xv.z * pd[k + 2] + xv.w * pd[k + 3];
            }
#pragma unroll
            for (int off = 16; off; off >>= 1) {
                s += __shfl_xor_sync(0xffffffffu, s, off);
                d += __shfl_xor_sync(0xffffffffu, d, off);
            }
            if (lane == 0) {
                s += cs;
                d += cd;
                g_s[i] = s;
                g_d[i] = d;
                unsigned int key = float_key(d);
                g_dkey[i] = ((unsigned long long)key << 32) | (unsigned int)i;
                kmn = min(kmn, key);
                kmx = max(kmx, key);
            }
        }
        if (lane == 0) {
            atomicMin(&g_kmin, kmn);
            atomicMax(&g_kmax, kmx);
        }
        grid_barrier(SORT_BLOCKS, &g_cnt1, &g_gen1);

        // ---- hist ----
        const int i = sbid * 256 + tid;
        unsigned long long kj = g_dkey[i];
        unsigned int key  = (unsigned int)(kj >> 32);
        unsigned int kmin = g_kmin;
        unsigned long long range = (unsigned long long)(g_kmax - kmin) + 1ull;
        int bin = (int)(((unsigned long long)(key - kmin) * NBUK) / range);
        int pos = atomicAdd(&g_hist[bin], 1);
        grid_barrier(SORT_BLOCKS, &g_cnt1, &g_gen1);

        // ---- scan 4096 bins (first sort block) ----
        if (sbid == 0) {
            __shared__ int ws[8];
            int base = tid * 16;
            int loc[16];
            int s = 0;
#pragma unroll
            for (int q = 0; q < 16; q++) { loc[q] = g_hist[base + q]; s += loc[q]; }
            int sc2 = s;
#pragma unroll
            for (int off = 1; off < 32; off <<= 1) {
                int o = __shfl_up_sync(0xffffffffu, sc2, off);
                if (lane >= off) sc2 += o;
            }
            if (lane == 31) ws[wid] = sc2;
            __syncthreads();
            if (tid == 0) {
                int run = 0;
#pragma unroll
                for (int q = 0; q < 8; q++) { int t2 = ws[q]; ws[q] = run; run += t2; }
            }
            __syncthreads();
            int run = ws[wid] + sc2 - s;
#pragma unroll
            for (int q = 0; q < 16; q++) { g_hstart[base + q] = run; run += loc[q]; }
        }
        grid_barrier(SORT_BLOCKS, &g_cnt1, &g_gen1);

        // ---- place ----
        int st = g_hstart[bin];
        g_bkeys[st + pos] = kj;
        grid_barrier(SORT_BLOCKS, &g_cnt1, &g_gen1);

        // ---- rank + inverse perm ----
        int cnt = g_hist[bin];
        int c = 0;
        for (int q = 0; q < cnt; q++) c += (g_bkeys[st + q] < kj) ? 1 : 0;
        int r = st + c;
        float d = g_d[i];
        g_inv[r]     = i;
        g_sortedD[r] = d;
        g_expD[r]    = expf(d);
    }
}

// ---------------- 3) fused scans: TR=32 local + parallel totals --------------
__global__ void __launch_bounds__(256) scanAB_kernel() {
    int b    = blockIdx.x;
    int tid  = threadIdx.x;
    int base = b * TR;
    __shared__ int   jidx[TR];
    __shared__ float ed[TR];
    if (tid < TR) {
        jidx[tid] = g_inv[base + tid];
        ed[tid]   = g_expD[base + tid];
    }
    __syncthreads();

    if (tid < 128) {
        int f = tid;
        float acc = 0.f;
#pragma unroll
        for (int bt = 0; bt < 2; bt++) {
            float vals[16];
#pragma unroll
            for (int q = 0; q < 16; q++)
                vals[q] = g_z[(size_t)jidx[bt * 16 + q] * FEAT + f];
#pragma unroll
            for (int q = 0; q < 16; q++) {
                g_S0[(size_t)(base + bt * 16 + q) * FEAT + f] = acc;
                acc += vals[q];
            }
        }
        g_T0[b * FEAT + f] = acc;

        if (f < 32) {
            float suf = ed[f];
#pragma unroll
            for (int off = 1; off < 32; off <<= 1) {
                float t2 = __shfl_down_sync(0xffffffffu, suf, off);
                if (f + off < 32) suf += t2;
            }
            g_c1[base + f] = suf;
            if (f == 0) g_Tc[b] = suf;
        }
    } else {
        int f = tid - 128;
        float accS = 0.f;
#pragma unroll
        for (int bt = 1; bt >= 0; bt--) {
            float vals[16];
#pragma unroll
            for (int q = 0; q < 16; q++)
                vals[q] = ed[bt * 16 + q] * g_z[(size_t)jidx[bt * 16 + q] * FEAT + f];
#pragma unroll
            for (int q = 15; q >= 0; q--) {
                accS += vals[q];
                g_SufE[(size_t)(base + bt * 16 + q) * FEAT + f] = accS;
            }
        }
        g_TS[b * FEAT + f] = accS;
    }

    grid_barrier(NBR, &g_cnt2, &g_gen2);

    if (b < 128) {
        int f = b;
        bool a2 = tid < NBR / 2;
        float v0a = 0.f, v0b = 0.f, vSa = 0.f, vSb = 0.f;
        if (a2) {
            v0a = g_T0[(2 * tid)     * FEAT + f];
            v0b = g_T0[(2 * tid + 1) * FEAT + f];
            vSa = g_TS[(2 * tid)     * FEAT + f];
            vSb = g_TS[(2 * tid + 1) * FEAT + f];
        }
        float p0 = v0a + v0b, pS = vSa + vSb;
        float i0 = p0, iS = pS;
        int lane = tid & 31, wid = tid >> 5;
#pragma unroll
        for (int off = 1; off < 32; off <<= 1) {
            float a0 = __shfl_up_sync(0xffffffffu, i0, off);
            float aS = __shfl_up_sync(0xffffffffu, iS, off);
            if (lane >= off) { i0 += a0; iS += aS; }
        }
        __shared__ float w0[8], wS[8];
        __shared__ float tot0s, totSs;
        if (lane == 31) { w0[wid] = i0; wS[wid] = iS; }
        __syncthreads();
        if (tid == 0) {
            float r0 = 0.f, rS = 0.f;
#pragma unroll
            for (int q = 0; q < 8; q++) {
                float t0 = w0[q], tS = wS[q];
                w0[q] = r0; wS[q] = rS;
                r0 += t0; rS += tS;
            }
            tot0s = r0; totSs = rS;
        }
        __syncthreads();
        i0 += w0[wid];
        iS += wS[wid];
        if (a2) {
            float e0 = i0 - p0;
            float eS = iS - pS;
            g_off0[(2 * tid)     * FEAT + f] = e0;
            g_off0[(2 * tid + 1) * FEAT + f] = e0 + v0a;
            g_offS[(2 * tid)     * FEAT + f] = totSs - (eS + vSa);
            g_offS[(2 * tid + 1) * FEAT + f] = totSs - (eS + vSa + vSb);
        }
        if (tid == 0) {
            g_off0[NBR * FEAT + f] = tot0s;
            g_offS[NBR * FEAT + f] = 0.f;
            g_S0[(size_t)NROW * FEAT + f]   = 0.f;
            g_SufE[(size_t)NROW * FEAT + f] = 0.f;
        }
    } else if (b == 128) {
        bool a2 = tid < NBR / 2;
        float vCa = 0.f, vCb = 0.f;
        if (a2) {
            vCa = g_Tc[2 * tid];
            vCb = g_Tc[2 * tid + 1];
        }
        float pC = vCa + vCb;
        float iC = pC;
        int lane = tid & 31, wid = tid >> 5;
#pragma unroll
        for (int off = 1; off < 32; off <<= 1) {
            float a = __shfl_up_sync(0xffffffffu, iC, off);
            if (lane >= off) iC += a;
        }
        __shared__ float wc[8];
        __shared__ float totc;
        if (lane == 31) wc[wid] = iC;
        __syncthreads();
        if (tid == 0) {
            float r = 0.f;
#pragma unroll
            for (int q = 0; q < 8; q++) { float t2 = wc[q]; wc[q] = r; r += t2; }
            totc = r;
        }
        __syncthreads();
        iC += wc[wid];
        if (a2) {
            float eC = iC - pC;
            g_offc[2 * tid]     = totc - (eC + vCa);
            g_offc[2 * tid + 1] = totc - (eC + vCa + vCb);
        }
        if (tid == 0) { g_offc[NBR] = 0.f; g_c1[NROW] = 0.f; }
    }
}

// ---------------- 4) combine: warp per row (4 rows/block) --------------------
__global__ void __launch_bounds__(128) combine_kernel(float* __restrict__ out) {
    int w    = threadIdx.x >> 5;
    int lane = threadIdx.x & 31;
    int i    = blockIdx.x * 4 + w;
    int f4   = lane * 4;

    float s = g_s[i];
    float thr = -s;
    int lo = 0, hi = NROW;
#pragma unroll 1
    while (lo < hi) {
        int mid = (lo + hi) >> 1;
        if (g_sortedD[mid] <= thr) lo = mid + 1;
        else hi = mid;
    }
    int k   = lo;
    int blk = k >> 5;

    float dmax  = g_sortedD[NROW - 1];
    float m     = fmaxf(0.f, s + dmax);
    float alpha = expf(s - m);
    float beta  = expf(-m);
    float den   = alpha * (g_offc[blk] + g_c1[k]) + beta * (float)k;
    float rden  = 1.f / den;

    float4 SufE = *(const float4*)&g_SufE[(size_t)k * FEAT + f4];
    float4 S0   = *(const float4*)&g_S0[(size_t)k * FEAT + f4];
    float4 offS = *(const float4*)&g_offS[(size_t)blk * FEAT + f4];
    float4 off0 = *(const float4*)&g_off0[(size_t)blk * FEAT + f4];
    float4 zv   = *(const float4*)&g_z[(size_t)i * FEAT + f4];

    float z2[4];
    z2[0] = (alpha * (offS.x + SufE.x) + beta * (off0.x + S0.x)) * rden + zv.x;
    z2[1] = (alpha * (offS.y + SufE.y) + beta * (off0.y + S0.y)) * rden + zv.y;
    z2[2] = (alpha * (offS.z + SufE.z) + beta * (off0.z + S0.z)) * rden + zv.z;
    z2[3] = (alpha * (offS.w + SufE.w) + beta * (off0.w + S0.w)) * rden + zv.w;

    float mx = fmaxf(fmaxf(z2[0], z2[1]), fmaxf(z2[2], z2[3]));
#pragma unroll
    for (int off = 16; off; off >>= 1) mx = fmaxf(mx, __shfl_xor_sync(0xffffffffu, mx, off));
    float e[4];
    float sm = 0.f;
#pragma unroll
    for (int q = 0; q < 4; q++) { e[q] = expf(z2[q] - mx); sm += e[q]; }
#pragma unroll
    for (int off = 16; off; off >>= 1) sm += __shfl_xor_sync(0xffffffffu, sm, off);
    float rs = 1.f / sm;
    float4 o = {e[0] * rs, e[1] * rs, e[2] * rs, e[3] * rs};
    *(float4*)&out[(size_t)i * FEAT + f4] = o;
}

// ---------------- launch ------------------------------------------------------
extern "C" void kernel_launch(void* const* d_in, const int* in_sizes, int n_in,
                              void* d_out, int out_size) {
    const float* x   = (const float*)d_in[0];   // [12288, 512]
    const float* v   = (const float*)d_in[1];   // [128, 512]
    const float* g   = (const float*)d_in[2];   // [128]
    const float* b   = (const float*)d_in[3];   // [128]
    const float* att = (const float*)d_in[4];   // [256]
    float* out = (float*)d_out;                 // [12288, 128]

    const int smem = (2 * ABUF + 4 * BBUF) * 2;   // 92160 bytes
    cudaFuncSetAttribute(fused_kernel, cudaFuncAttributeMaxDynamicSharedMemorySize, smem);

    prep_kernel<<<4, 1024>>>(v, g, att);
    fused_kernel<<<GEMM_BLOCKS + SORT_BLOCKS, 256, smem>>>(x, b, att);
    scanAB_kernel<<<NBR, 256>>>();
    combine_kernel<<<NROW / 4, 128>>>(out);
}

// round 15
// speedup vs baseline: 1.8514x; 1.8514x over previous
#include <cuda_runtime.h>
#include <cuda_bf16.h>
#include <math.h>
#include <stdint.h>

#define NROW 12288
#define DIM  512
#define FEAT 128
#define TR   64            // rows per scan tile
#define NBR  192           // NROW / TR
#define SA   72            // padded bf16 row stride in smem (conflict-free)
#define NBUK 4096
#define ABUF (64 * SA)     // ushorts per A array
#define BBUF (128 * SA)    // ushorts per B array

// ---------------- scratch (device globals; allocations forbidden) -----------
__device__ float g_scale[FEAT];
__device__ unsigned short g_vhi[FEAT * DIM];
__device__ unsigned short g_vlo[FEAT * DIM];
__device__ float g_z[NROW * FEAT];
__device__ float g_s[NROW];
__device__ float g_d[NROW];
__device__ unsigned long long g_dkey[NROW];
__device__ int   g_bin[NROW];
__device__ int   g_hist[NBUK];
__device__ int   g_hcur[NBUK];
__device__ int   g_hstart[NBUK];
__device__ unsigned long long g_bkeys[NROW];
__device__ unsigned int g_kmin, g_kmax;
__device__ int   g_inv[NROW];
__device__ float g_sortedD[NROW];
__device__ float g_expD[NROW];
__device__ float g_S0[(NROW + 1) * FEAT];
__device__ float g_SufE[(NROW + 1) * FEAT];
__device__ float g_c1[NROW + 1];
__device__ float g_T0[NBR * FEAT];
__device__ float g_TS[NBR * FEAT];
__device__ float g_Tc[NBR];
__device__ float g_off0[(NBR + 1) * FEAT];
__device__ float g_offS[(NBR + 1) * FEAT];
__device__ float g_offc[NBR + 1];
__device__ int   g_cnt1, g_gen1;   // sort-kernel barrier
__device__ int   g_cnt2, g_gen2;   // scan-kernel barrier

// ---------------- helpers -----------------------------------------------------
__device__ __forceinline__ void grid_barrier(int expected, int* cnt, int* gen) {
    __syncthreads();
    if (threadIdx.x == 0) {
        int g0 = *((volatile int*)gen);
        __threadfence();
        if (atomicAdd(cnt, 1) == expected - 1) {
            *((volatile int*)cnt) = 0;
            __threadfence();
            atomicAdd(gen, 1);
        } else {
            while (*((volatile int*)gen) == g0) { __nanosleep(64); }
            __threadfence();
        }
    }
    __syncthreads();
}
__device__ __forceinline__ unsigned int float_key(float x) {
    unsigned int u = __float_as_uint(x);
    return (u & 0x80000000u) ? ~u : (u | 0x80000000u);
}
__device__ __forceinline__ uint32_t smem_u32(const void* p) {
    uint32_t a;
    asm("{ .reg .u64 t; cvta.to.shared.u64 t, %1; cvt.u32.u64 %0, t; }" : "=r"(a) : "l"(p));
    return a;
}
__device__ __forceinline__ void mma_bf16(float* c, const uint32_t* a,
                                         uint32_t b0, uint32_t b1) {
    asm volatile(
        "mma.sync.aligned.m16n8k16.row.col.f32.bf16.bf16.f32 "
        "{%0,%1,%2,%3}, {%4,%5,%6,%7}, {%8,%9}, {%0,%1,%2,%3};"
        : "+f"(c[0]), "+f"(c[1]), "+f"(c[2]), "+f"(c[3])
        : "r"(a[0]), "r"(a[1]), "r"(a[2]), "r"(a[3]), "r"(b0), "r"(b1));
}
#define LDSM4(r, addr) \
    asm volatile("ldmatrix.sync.aligned.m8n8.x4.shared.b16 {%0,%1,%2,%3}, [%4];" \
        : "=r"((r)[0]), "=r"((r)[1]), "=r"((r)[2]), "=r"((r)[3]) : "r"(addr))
__device__ __forceinline__ void cp16(uint32_t s, const void* g) {
    asm volatile("cp.async.cg.shared.global [%0], [%1], 16;" :: "r"(s), "l"(g));
}

// ---------------- 1) prep: scale + v split + hist zero + key-range reset -----
__global__ void prep_kernel(const float* __restrict__ v, const float* __restrict__ g) {
    int f = blockIdx.x;
    int t = threadIdx.x;
    int idx = f * 128 + t;
    if (idx < NBUK) g_hist[idx] = 0;
    else if (idx < 2 * NBUK) g_hcur[idx - NBUK] = 0;
    else if (idx == 2 * NBUK) { g_kmin = 0xFFFFFFFFu; g_kmax = 0u; }

    float ss = 0.f;
    for (int q = t; q < DIM; q += 128) {
        float vv = v[(size_t)f * DIM + q];
        ss += vv * vv;
    }
    __shared__ float red[4];
    __shared__ float s_sc;
    for (int off = 16; off; off >>= 1) ss += __shfl_xor_sync(0xffffffffu, ss, off);
    if ((t & 31) == 0) red[t >> 5] = ss;
    __syncthreads();
    if (t == 0) {
        float sc = g[f] / sqrtf(red[0] + red[1] + red[2] + red[3]);
        g_scale[f] = sc;
        s_sc = sc;
    }
    __syncthreads();
    float sc = s_sc;
    for (int k = t; k < DIM; k += 128) {
        float val = v[(size_t)f * DIM + k] * sc;
        __nv_bfloat16 h = __float2bfloat16(val);
        float lo = val - __bfloat162float(h);
        g_vhi[f * DIM + k] = __bfloat16_as_ushort(h);
        g_vlo[f * DIM + k] = __bfloat16_as_ushort(__float2bfloat16(lo));
    }
}

// ---------------- 2) HMMA GEMM: cp.async double-buffered B, prefetched A -----
__global__ void __launch_bounds__(256, 2) gemm_mma_kernel(const float* __restrict__ x,
                                                          const float* __restrict__ b,
                                                          const float* __restrict__ att) {
    extern __shared__ unsigned short sm[];
    unsigned short* aH = sm;                         // 64*SA
    unsigned short* aL = sm + ABUF;
    // B buffers: [bH0 | bL0 | bH1 | bL1]
    unsigned short* bB = sm + 2 * ABUF;
    float* sdp = (float*)sm;                         // reused after mainloop

    const int tid  = threadIdx.x;
    const int w    = tid >> 5;
    const int lane = tid & 31;
    const int g    = lane >> 2;
    const int tig  = lane & 3;
    const int mw   = w & 3;
    const int nw   = w >> 2;
    const int bm   = blockIdx.x * 64;
    const int rb   = mw * 16;
    const int n0   = nw * 64;

    const uint32_t aHs = smem_u32(aH), aLs = smem_u32(aL);
    const uint32_t bBs = smem_u32(bB);
    const uint32_t BOFF = 2 * BBUF * 2;              // bytes per (hi,lo) buffer pair

    const int rA = (lane & 7) + ((lane >> 3) & 1) * 8;
    const int cA = (lane >> 4) * 8;
    const uint32_t aAdH = aHs + ((rb + rA) * SA + cA) * 2;
    const uint32_t aAdL = aLs + ((rb + rA) * SA + cA) * 2;
    const int rB = (lane & 7) + (lane >> 4) * 8;
    const int cB = ((lane >> 3) & 1) * 8;
    uint32_t bAdH[4], bAdL[4];
#pragma unroll
    for (int j = 0; j < 4; j++) {
        bAdH[j] = bBs + ((n0 + j * 16 + rB) * SA + cB) * 2;
        bAdL[j] = bBs + BBUF * 2 + ((n0 + j * 16 + rB) * SA + cB) * 2;
    }

    // B staging coords
    const int brr = tid >> 3;        // row 0..31 step; covers 128 rows in 4 passes
    const int bu  = tid & 7;         // 16B unit

    float acc[8][4];
#pragma unroll
    for (int nt = 0; nt < 8; nt++)
#pragma unroll
        for (int q = 0; q < 4; q++) acc[nt][q] = 0.f;

    // ---- prologue: issue B(0), preload A(0) regs ----
#pragma unroll
    for (int p = 0; p < 4; p++) {
        int r = p * 32 + brr;
        size_t gv = (size_t)r * DIM + bu * 8;
        uint32_t so = (uint32_t)(r * SA + bu * 8) * 2;
        cp16(bBs + so, g_vhi + gv);
        cp16(bBs + BBUF * 2 + so, g_vlo + gv);
    }
    asm volatile("cp.async.commit_group;" ::: "memory");

    float4 xr[4];
#pragma unroll
    for (int p = 0; p < 4; p++) {
        int li = tid + p * 256;
        int r  = li >> 4;
        int c4 = (li & 15) * 4;
        xr[p] = *(const float4*)(x + (size_t)(bm + r) * DIM + c4);
    }

    for (int c = 0; c < 8; c++) {
        const uint32_t boff = (uint32_t)(c & 1) * BOFF;
        // ---- convert & store A(c) from regs ----
#pragma unroll
        for (int p = 0; p < 4; p++) {
            int li = tid + p * 256;
            int r  = li >> 4;
            int c4 = (li & 15) * 4;
            float4 xv = xr[p];
            __nv_bfloat16 h0 = __float2bfloat16(xv.x);
            __nv_bfloat16 h1 = __float2bfloat16(xv.y);
            __nv_bfloat16 h2 = __float2bfloat16(xv.z);
            __nv_bfloat16 h3 = __float2bfloat16(xv.w);
            uint2 hv, lv;
            hv.x = ((uint32_t)__bfloat16_as_ushort(h1) << 16) | __bfloat16_as_ushort(h0);
            hv.y = ((uint32_t)__bfloat16_as_ushort(h3) << 16) | __bfloat16_as_ushort(h2);
            __nv_bfloat16 l0 = __float2bfloat16(xv.x - __bfloat162float(h0));
            __nv_bfloat16 l1 = __float2bfloat16(xv.y - __bfloat162float(h1));
            __nv_bfloat16 l2 = __float2bfloat16(xv.z - __bfloat162float(h2));
            __nv_bfloat16 l3 = __float2bfloat16(xv.w - __bfloat162float(h3));
            lv.x = ((uint32_t)__bfloat16_as_ushort(l1) << 16) | __bfloat16_as_ushort(l0);
            lv.y = ((uint32_t)__bfloat16_as_ushort(l3) << 16) | __bfloat16_as_ushort(l2);
            *(uint2*)&aH[r * SA + c4] = hv;
            *(uint2*)&aL[r * SA + c4] = lv;
        }
        // ---- issue B(c+1) into other buffer ----
        if (c < 7) {
            const int k0n = (c + 1) * 64;
            const uint32_t bo2 = (uint32_t)((c + 1) & 1) * BOFF;
#pragma unroll
            for (int p = 0; p < 4; p++) {
                int r = p * 32 + brr;
                size_t gv = (size_t)r * DIM + k0n + bu * 8;
                uint32_t so = (uint32_t)(r * SA + bu * 8) * 2;
                cp16(bBs + bo2 + so, g_vhi + gv);
                cp16(bBs + bo2 + BBUF * 2 + so, g_vlo + gv);
            }
            asm volatile("cp.async.commit_group;" ::: "memory");
            asm volatile("cp.async.wait_group 1;" ::: "memory");
        } else {
            asm volatile("cp.async.wait_group 0;" ::: "memory");
        }
        __syncthreads();

        // ---- prefetch A(c+1) regs (overlaps with MMA below) ----
        if (c < 7) {
            const int k0n = (c + 1) * 64;
#pragma unroll
            for (int p = 0; p < 4; p++) {
                int li = tid + p * 256;
                int r  = li >> 4;
                int c4 = (li & 15) * 4;
                xr[p] = *(const float4*)(x + (size_t)(bm + r) * DIM + k0n + c4);
            }
        }

        // ---- MMA over buffer (c&1) ----
#pragma unroll
        for (int kt = 0; kt < 4; kt++) {
            uint32_t ah[4], al[4];
            LDSM4(ah, aAdH + kt * 32);
            LDSM4(al, aAdL + kt * 32);
#pragma unroll
            for (int j = 0; j < 4; j++) {
                uint32_t bh[4], bl[4];
                LDSM4(bh, bAdH[j] + boff + kt * 32);
                LDSM4(bl, bAdL[j] + boff + kt * 32);
                mma_bf16(acc[2 * j],     ah, bh[0], bh[1]);
                mma_bf16(acc[2 * j],     ah, bl[0], bl[1]);
                mma_bf16(acc[2 * j],     al, bh[0], bh[1]);
                mma_bf16(acc[2 * j + 1], ah, bh[2], bh[3]);
                mma_bf16(acc[2 * j + 1], ah, bl[2], bl[3]);
                mma_bf16(acc[2 * j + 1], al, bh[2], bh[3]);
            }
        }
        __syncthreads();
    }

    // ---- epilogue ----
    float sv[2] = {0.f, 0.f}, dv[2] = {0.f, 0.f};
    const int row0 = bm + rb + g;
#pragma unroll
    for (int nt = 0; nt < 8; nt++) {
        int cb = n0 + nt * 8 + tig * 2;
        float2 bb = *(const float2*)&b[cb];
        float2 as = *(const float2*)&att[cb];
        float2 ad = *(const float2*)&att[FEAT + cb];
        float z0 = acc[nt][0] + bb.x;
        float z1 = acc[nt][1] + bb.y;
        float z2 = acc[nt][2] + bb.x;
        float z3 = acc[nt][3] + bb.y;
        *(float2*)&g_z[(size_t)row0 * FEAT + cb]       = make_float2(z0, z1);
        *(float2*)&g_z[(size_t)(row0 + 8) * FEAT + cb] = make_float2(z2, z3);
        sv[0] += z0 * as.x + z1 * as.y;
        sv[1] += z2 * as.x + z3 * as.y;
        dv[0] += z0 * ad.x + z1 * ad.y;
        dv[1] += z2 * ad.x + z3 * ad.y;
    }
#pragma unroll
    for (int h = 0; h < 2; h++) {
        sv[h] += __shfl_xor_sync(0xffffffffu, sv[h], 1);
        sv[h] += __shfl_xor_sync(0xffffffffu, sv[h], 2);
        dv[h] += __shfl_xor_sync(0xffffffffu, dv[h], 1);
        dv[h] += __shfl_xor_sync(0xffffffffu, dv[h], 2);
    }
    if (tig == 0) {
        int rl0 = rb + g;
        sdp[(nw * 64 + rl0) * 2 + 0]     = sv[0];
        sdp[(nw * 64 + rl0) * 2 + 1]     = dv[0];
        sdp[(nw * 64 + rl0 + 8) * 2 + 0] = sv[1];
        sdp[(nw * 64 + rl0 + 8) * 2 + 1] = dv[1];
    }
    __syncthreads();
    if (tid < 64) {
        float s = sdp[tid * 2]     + sdp[(64 + tid) * 2];
        float d = sdp[tid * 2 + 1] + sdp[(64 + tid) * 2 + 1];
        int row = bm + tid;
        g_s[row] = s;
        g_d[row] = d;
        unsigned int key = float_key(d);
        g_dkey[row] = ((unsigned long long)key << 32) | (unsigned int)row;
        unsigned int kmn = key, kmx = key;
#pragma unroll
        for (int off = 16; off; off >>= 1) {
            kmn = min(kmn, __shfl_xor_sync(0xffffffffu, kmn, off));
            kmx = max(kmx, __shfl_xor_sync(0xffffffffu, kmx, off));
        }
        if (lane == 0) {
            atomicMin(&g_kmin, kmn);
            atomicMax(&g_kmax, kmx);
        }
    }
}

// ---------------- 3) fused sort: hist -> scan -> place -> rank ---------------
__global__ void __launch_bounds__(256) sort_kernel() {
    const int nb  = 48;
    const int tid = threadIdx.x;
    const int bid = blockIdx.x;
    const int i   = bid * 256 + tid;

    unsigned long long kj = g_dkey[i];
    unsigned int key  = (unsigned int)(kj >> 32);
    unsigned int kmin = g_kmin;
    unsigned long long range = (unsigned long long)(g_kmax - kmin) + 1ull;
    int bin = (int)(((unsigned long long)(key - kmin) * NBUK) / range);
    g_bin[i] = bin;
    atomicAdd(&g_hist[bin], 1);
    grid_barrier(nb, &g_cnt1, &g_gen1);

    if (bid == 0) {
        __shared__ int ws[8];
        int base = tid * 16;
        int loc[16];
        int s = 0;
#pragma unroll
        for (int q = 0; q < 16; q++) { loc[q] = g_hist[base + q]; s += loc[q]; }
        int lane = tid & 31, wid = tid >> 5;
        int sc = s;
#pragma unroll
        for (int off = 1; off < 32; off <<= 1) {
            int o = __shfl_up_sync(0xffffffffu, sc, off);
            if (lane >= off) sc += o;
        }
        if (lane == 31) ws[wid] = sc;
        __syncthreads();
        if (tid == 0) {
            int run = 0;
#pragma unroll
            for (int q = 0; q < 8; q++) { int t2 = ws[q]; ws[q] = run; run += t2; }
        }
        __syncthreads();
        int run = ws[wid] + sc - s;
#pragma unroll
        for (int q = 0; q < 16; q++) { g_hstart[base + q] = run; run += loc[q]; }
    }
    grid_barrier(nb, &g_cnt1, &g_gen1);

    int pos = atomicAdd(&g_hcur[bin], 1);
    g_bkeys[g_hstart[bin] + pos] = kj;
    grid_barrier(nb, &g_cnt1, &g_gen1);

    int st  = g_hstart[bin];
    int cnt = g_hist[bin];
    int c = 0;
    for (int q = 0; q < cnt; q++) c += (g_bkeys[st + q] < kj) ? 1 : 0;
    int r = st + c;
    float d = g_d[i];
    g_inv[r]     = i;
    g_sortedD[r] = d;
    g_expD[r]    = expf(d);
}

// ---------------- 4) fused scans: MLP-batched local + parallel totals --------
__global__ void __launch_bounds__(256) scanAB_kernel() {
    int b    = blockIdx.x;
    int tid  = threadIdx.x;
    int base = b * TR;
    __shared__ int   jidx[TR];
    __shared__ float ed[TR];
    if (tid < TR) {
        jidx[tid] = g_inv[base + tid];
        ed[tid]   = g_expD[base + tid];
    }
    __syncthreads();

    if (tid < 128) {
        int f = tid;
        float acc = 0.f;
#pragma unroll
        for (int bt = 0; bt < 4; bt++) {
            float vals[16];
#pragma unroll
            for (int q = 0; q < 16; q++)
                vals[q] = g_z[(size_t)jidx[bt * 16 + q] * FEAT + f];
#pragma unroll
            for (int q = 0; q < 16; q++) {
                g_S0[(size_t)(base + bt * 16 + q) * FEAT + f] = acc;
                acc += vals[q];
            }
        }
        g_T0[b * FEAT + f] = acc;

        if (f < 32) {
            float v0 = ed[2 * f], v1 = ed[2 * f + 1];
            float seg = v0 + v1;
            float suf = seg;
#pragma unroll
            for (int off = 1; off < 32; off <<= 1) {
                float t2 = __shfl_down_sync(0xffffffffu, suf, off);
                if (f + off < 32) suf += t2;
            }
            float excl = suf - seg;
            g_c1[base + 2 * f + 1] = excl + v1;
            g_c1[base + 2 * f]     = excl + v1 + v0;
            if (f == 0) g_Tc[b] = suf;
        }
    } else {
        int f = tid - 128;
        float accS = 0.f;
#pragma unroll
        for (int bt = 3; bt >= 0; bt--) {
            float vals[16];
#pragma unroll
            for (int q = 0; q < 16; q++)
                vals[q] = ed[bt * 16 + q] * g_z[(size_t)jidx[bt * 16 + q] * FEAT + f];
#pragma unroll
            for (int q = 15; q >= 0; q--) {
                accS += vals[q];
                g_SufE[(size_t)(base + bt * 16 + q) * FEAT + f] = accS;
            }
        }
        g_TS[b * FEAT + f] = accS;
    }

    grid_barrier(NBR, &g_cnt2, &g_gen2);

    if (b < 128) {
        int f = b;
        bool act = tid < NBR;
        float v0 = act ? g_T0[tid * FEAT + f] : 0.f;
        float vS = act ? g_TS[tid * FEAT + f] : 0.f;
        float i0 = v0, iS = vS;
        int lane = tid & 31, wid = tid >> 5;
#pragma unroll
        for (int off = 1; off < 32; off <<= 1) {
            float a0 = __shfl_up_sync(0xffffffffu, i0, off);
            float aS = __shfl_up_sync(0xffffffffu, iS, off);
            if (lane >= off) { i0 += a0; iS += aS; }
        }
        __shared__ float w0[8], wS[8];
        __shared__ float tot0s, totSs;
        if (lane == 31) { w0[wid] = i0; wS[wid] = iS; }
        __syncthreads();
        if (tid == 0) {
            float r0 = 0.f, rS = 0.f;
#pragma unroll
            for (int q = 0; q < 8; q++) {
                float t0 = w0[q], tS = wS[q];
                w0[q] = r0; wS[q] = rS;
                r0 += t0; rS += tS;
            }
            tot0s = r0; totSs = rS;
        }
        __syncthreads();
        i0 += w0[wid];
        iS += wS[wid];
        if (act) {
            g_off0[tid * FEAT + f] = i0 - v0;
            g_offS[tid * FEAT + f] = totSs - iS;
        }
        if (tid == 0) {
            g_off0[NBR * FEAT + f] = tot0s;
            g_offS[NBR * FEAT + f] = 0.f;
            g_S0[(size_t)NROW * FEAT + f]   = 0.f;
            g_SufE[(size_t)NROW * FEAT + f] = 0.f;
        }
    } else if (b == 128) {
        bool act = tid < NBR;
        float vc = act ? g_Tc[tid] : 0.f;
        float ic = vc;
        int lane = tid & 31, wid = tid >> 5;
#pragma unroll
        for (int off = 1; off < 32; off <<= 1) {
            float a = __shfl_up_sync(0xffffffffu, ic, off);
            if (lane >= off) ic += a;
        }
        __shared__ float wc[8];
        __shared__ float totc;
        if (lane == 31) wc[wid] = ic;
        __syncthreads();
        if (tid == 0) {
            float r = 0.f;
#pragma unroll
            for (int q = 0; q < 8; q++) { float t2 = wc[q]; wc[q] = r; r += t2; }
            totc = r;
        }
        __syncthreads();
        ic += wc[wid];
        if (act) g_offc[tid] = totc - ic;
        if (tid == 0) { g_offc[NBR] = 0.f; g_c1[NROW] = 0.f; }
    }
}

// ---------------- 5) combine: warp per row, shuffle-only softmax -------------
__global__ void __launch_bounds__(128) combine_kernel(float* __restrict__ out) {
    int w    = threadIdx.x >> 5;
    int lane = threadIdx.x & 31;
    int i    = blockIdx.x * 4 + w;
    int f4   = lane * 4;

    float s = g_s[i];
    float thr = -s;
    int lo = 0, hi = NROW;
#pragma unroll 1
    while (lo < hi) {
        int mid = (lo + hi) >> 1;
        if (g_sortedD[mid] <= thr) lo = mid + 1;
        else hi = mid;
    }
    int k   = lo;
    int blk = k >> 6;

    float dmax  = g_sortedD[NROW - 1];
    float m     = fmaxf(0.f, s + dmax);
    float alpha = expf(s - m);
    float beta  = expf(-m);
    float den   = alpha * (g_offc[blk] + g_c1[k]) + beta * (float)k;
    float rden  = 1.f / den;

    float4 SufE = *(const float4*)&g_SufE[(size_t)k * FEAT + f4];
    float4 S0   = *(const float4*)&g_S0[(size_t)k * FEAT + f4];
    float4 offS = *(const float4*)&g_offS[(size_t)blk * FEAT + f4];
    float4 off0 = *(const float4*)&g_off0[(size_t)blk * FEAT + f4];
    float4 zv   = *(const float4*)&g_z[(size_t)i * FEAT + f4];

    float z2[4];
    z2[0] = (alpha * (offS.x + SufE.x) + beta * (off0.x + S0.x)) * rden + zv.x;
    z2[1] = (alpha * (offS.y + SufE.y) + beta * (off0.y + S0.y)) * rden + zv.y;
    z2[2] = (alpha * (offS.z + SufE.z) + beta * (off0.z + S0.z)) * rden + zv.z;
    z2[3] = (alpha * (offS.w + SufE.w) + beta * (off0.w + S0.w)) * rden + zv.w;

    float mx = fmaxf(fmaxf(z2[0], z2[1]), fmaxf(z2[2], z2[3]));
#pragma unroll
    for (int off = 16; off; off >>= 1) mx = fmaxf(mx, __shfl_xor_sync(0xffffffffu, mx, off));
    float e[4];
    float sm = 0.f;
#pragma unroll
    for (int q = 0; q < 4; q++) { e[q] = expf(z2[q] - mx); sm += e[q]; }
#pragma unroll
    for (int off = 16; off; off >>= 1) sm += __shfl_xor_sync(0xffffffffu, sm, off);
    float rs = 1.f / sm;
    float4 o = {e[0] * rs, e[1] * rs, e[2] * rs, e[3] * rs};
    *(float4*)&out[(size_t)i * FEAT + f4] = o;
}

// ---------------- launch ------------------------------------------------------
extern "C" void kernel_launch(void* const* d_in, const int* in_sizes, int n_in,
                              void* d_out, int out_size) {
    const float* x   = (const float*)d_in[0];   // [12288, 512]
    const float* v   = (const float*)d_in[1];   // [128, 512]
    const float* g   = (const float*)d_in[2];   // [128]
    const float* b   = (const float*)d_in[3];   // [128]
    const float* att = (const float*)d_in[4];   // [256]
    float* out = (float*)d_out;                 // [12288, 128]

    const int smem = (2 * ABUF + 4 * BBUF) * 2;   // 92160 bytes
    cudaFuncSetAttribute(gemm_mma_kernel, cudaFuncAttributeMaxDynamicSharedMemorySize, smem);

    prep_kernel<<<FEAT, 128>>>(v, g);
    gemm_mma_kernel<<<NROW / 64, 256, smem>>>(x, b, att);
    sort_kernel<<<48, 256>>>();
    scanAB_kernel<<<NBR, 256>>>();
    combine_kernel<<<NROW / 4, 128>>>(out);
}

// round 16
// speedup vs baseline: 1.9055x; 1.0292x over previous
#include <cuda_runtime.h>
#include <cuda_bf16.h>
#include <math.h>
#include <stdint.h>

#define NROW 12288
#define DIM  512
#define FEAT 128
#define TR   64            // rows per scan tile
#define NBR  192           // NROW / TR
#define SA   72            // padded bf16 row stride in smem (conflict-free)
#define NBUK 4096
#define ABUF (64 * SA)     // ushorts per A array
#define BBUF (128 * SA)    // ushorts per B array

// ---------------- scratch (device globals; allocations forbidden) -----------
__device__ float g_scale[FEAT];
__device__ unsigned short g_vhi[FEAT * DIM];
__device__ unsigned short g_vlo[FEAT * DIM];
__device__ float g_z[NROW * FEAT];
__device__ float g_s[NROW];
__device__ float g_d[NROW];
__device__ unsigned long long g_dkey[NROW];
__device__ int   g_bin[NROW];
__device__ int   g_hist[NBUK];
__device__ int   g_hcur[NBUK];
__device__ int   g_hstart[NBUK];
__device__ unsigned long long g_bkeys[NROW];
__device__ unsigned int g_kmin, g_kmax;
__device__ int   g_inv[NROW];
__device__ float g_sortedD[NROW];
__device__ float g_expD[NROW];
__device__ float g_S0[(NROW + 1) * FEAT];
__device__ float g_SufE[(NROW + 1) * FEAT];
__device__ float g_c1[NROW + 1];
__device__ float g_T0[NBR * FEAT];
__device__ float g_TS[NBR * FEAT];
__device__ float g_Tc[NBR];
__device__ float g_off0[(NBR + 1) * FEAT];
__device__ float g_offS[(NBR + 1) * FEAT];
__device__ float g_offc[NBR + 1];
__device__ int   g_cnt1, g_gen1;   // sort-kernel barrier
__device__ int   g_cnt2, g_gen2;   // scan-kernel barrier

// ---------------- helpers -----------------------------------------------------
__device__ __forceinline__ void grid_barrier(int expected, int* cnt, int* gen) {
    __syncthreads();
    if (threadIdx.x == 0) {
        int g0 = *((volatile int*)gen);
        __threadfence();
        if (atomicAdd(cnt, 1) == expected - 1) {
            *((volatile int*)cnt) = 0;
            __threadfence();
            atomicAdd(gen, 1);
        } else {
            while (*((volatile int*)gen) == g0) { __nanosleep(64); }
            __threadfence();
        }
    }
    __syncthreads();
}
__device__ __forceinline__ unsigned int float_key(float x) {
    unsigned int u = __float_as_uint(x);
    return (u & 0x80000000u) ? ~u : (u | 0x80000000u);
}
__device__ __forceinline__ uint32_t smem_u32(const void* p) {
    uint32_t a;
    asm("{ .reg .u64 t; cvta.to.shared.u64 t, %1; cvt.u32.u64 %0, t; }" : "=r"(a) : "l"(p));
    return a;
}
__device__ __forceinline__ void mma_bf16(float* c, const uint32_t* a,
                                         uint32_t b0, uint32_t b1) {
    asm volatile(
        "mma.sync.aligned.m16n8k16.row.col.f32.bf16.bf16.f32 "
        "{%0,%1,%2,%3}, {%4,%5,%6,%7}, {%8,%9}, {%0,%1,%2,%3};"
        : "+f"(c[0]), "+f"(c[1]), "+f"(c[2]), "+f"(c[3])
        : "r"(a[0]), "r"(a[1]), "r"(a[2]), "r"(a[3]), "r"(b0), "r"(b1));
}
#define LDSM4(r, addr) \
    asm volatile("ldmatrix.sync.aligned.m8n8.x4.shared.b16 {%0,%1,%2,%3}, [%4];" \
        : "=r"((r)[0]), "=r"((r)[1]), "=r"((r)[2]), "=r"((r)[3]) : "r"(addr))
__device__ __forceinline__ void cp16(uint32_t s, const void* g) {
    asm volatile("cp.async.cg.shared.global [%0], [%1], 16;" :: "r"(s), "l"(g));
}

// ---------------- 1) prep: scale + v split + hist zero + key-range reset -----
__global__ void prep_kernel(const float* __restrict__ v, const float* __restrict__ g) {
    int f = blockIdx.x;
    int t = threadIdx.x;
    int idx = f * 128 + t;
    if (idx < NBUK) g_hist[idx] = 0;
    else if (idx < 2 * NBUK) g_hcur[idx - NBUK] = 0;
    else if (idx == 2 * NBUK) { g_kmin = 0xFFFFFFFFu; g_kmax = 0u; }

    float ss = 0.f;
    for (int q = t; q < DIM; q += 128) {
        float vv = v[(size_t)f * DIM + q];
        ss += vv * vv;
    }
    __shared__ float red[4];
    __shared__ float s_sc;
    for (int off = 16; off; off >>= 1) ss += __shfl_xor_sync(0xffffffffu, ss, off);
    if ((t & 31) == 0) red[t >> 5] = ss;
    __syncthreads();
    if (t == 0) {
        float sc = g[f] / sqrtf(red[0] + red[1] + red[2] + red[3]);
        g_scale[f] = sc;
        s_sc = sc;
    }
    __syncthreads();
    float sc = s_sc;
    for (int k = t; k < DIM; k += 128) {
        float val = v[(size_t)f * DIM + k] * sc;
        __nv_bfloat16 h = __float2bfloat16(val);
        float lo = val - __bfloat162float(h);
        g_vhi[f * DIM + k] = __bfloat16_as_ushort(h);
        g_vlo[f * DIM + k] = __bfloat16_as_ushort(__float2bfloat16(lo));
    }
}

// ---------------- 2) HMMA GEMM: cp.async double-buffered B, prefetched A -----
__global__ void __launch_bounds__(256, 2) gemm_mma_kernel(const float* __restrict__ x,
                                                          const float* __restrict__ b,
                                                          const float* __restrict__ att) {
    extern __shared__ unsigned short sm[];
    unsigned short* aH = sm;                         // 64*SA
    unsigned short* aL = sm + ABUF;
    // B buffers: [bH0 | bL0 | bH1 | bL1]
    unsigned short* bB = sm + 2 * ABUF;
    float* sdp = (float*)sm;                         // reused after mainloop

    const int tid  = threadIdx.x;
    const int w    = tid >> 5;
    const int lane = tid & 31;
    const int g    = lane >> 2;
    const int tig  = lane & 3;
    const int mw   = w & 3;
    const int nw   = w >> 2;
    const int bm   = blockIdx.x * 64;
    const int rb   = mw * 16;
    const int n0   = nw * 64;

    const uint32_t aHs = smem_u32(aH), aLs = smem_u32(aL);
    const uint32_t bBs = smem_u32(bB);
    const uint32_t BOFF = 2 * BBUF * 2;              // bytes per (hi,lo) buffer pair

    const int rA = (lane & 7) + ((lane >> 3) & 1) * 8;
    const int cA = (lane >> 4) * 8;
    const uint32_t aAdH = aHs + ((rb + rA) * SA + cA) * 2;
    const uint32_t aAdL = aLs + ((rb + rA) * SA + cA) * 2;
    const int rB = (lane & 7) + (lane >> 4) * 8;
    const int cB = ((lane >> 3) & 1) * 8;
    uint32_t bAdH[4], bAdL[4];
#pragma unroll
    for (int j = 0; j < 4; j++) {
        bAdH[j] = bBs + ((n0 + j * 16 + rB) * SA + cB) * 2;
        bAdL[j] = bBs + BBUF * 2 + ((n0 + j * 16 + rB) * SA + cB) * 2;
    }

    // B staging coords
    const int brr = tid >> 3;        // row 0..31 step; covers 128 rows in 4 passes
    const int bu  = tid & 7;         // 16B unit

    float acc[8][4];
#pragma unroll
    for (int nt = 0; nt < 8; nt++)
#pragma unroll
        for (int q = 0; q < 4; q++) acc[nt][q] = 0.f;

    // ---- prologue: issue B(0), preload A(0) regs ----
#pragma unroll
    for (int p = 0; p < 4; p++) {
        int r = p * 32 + brr;
        size_t gv = (size_t)r * DIM + bu * 8;
        uint32_t so = (uint32_t)(r * SA + bu * 8) * 2;
        cp16(bBs + so, g_vhi + gv);
        cp16(bBs + BBUF * 2 + so, g_vlo + gv);
    }
    asm volatile("cp.async.commit_group;" ::: "memory");

    float4 xr[4];
#pragma unroll
    for (int p = 0; p < 4; p++) {
        int li = tid + p * 256;
        int r  = li >> 4;
        int c4 = (li & 15) * 4;
        xr[p] = *(const float4*)(x + (size_t)(bm + r) * DIM + c4);
    }

    for (int c = 0; c < 8; c++) {
        const uint32_t boff = (uint32_t)(c & 1) * BOFF;
        // ---- convert & store A(c) from regs ----
#pragma unroll
        for (int p = 0; p < 4; p++) {
            int li = tid + p * 256;
            int r  = li >> 4;
            int c4 = (li & 15) * 4;
            float4 xv = xr[p];
            __nv_bfloat16 h0 = __float2bfloat16(xv.x);
            __nv_bfloat16 h1 = __float2bfloat16(xv.y);
            __nv_bfloat16 h2 = __float2bfloat16(xv.z);
            __nv_bfloat16 h3 = __float2bfloat16(xv.w);
            uint2 hv, lv;
            hv.x = ((uint32_t)__bfloat16_as_ushort(h1) << 16) | __bfloat16_as_ushort(h0);
            hv.y = ((uint32_t)__bfloat16_as_ushort(h3) << 16) | __bfloat16_as_ushort(h2);
            __nv_bfloat16 l0 = __float2bfloat16(xv.x - __bfloat162float(h0));
            __nv_bfloat16 l1 = __float2bfloat16(xv.y - __bfloat162float(h1));
            __nv_bfloat16 l2 = __float2bfloat16(xv.z - __bfloat162float(h2));
            __nv_bfloat16 l3 = __float2bfloat16(xv.w - __bfloat162float(h3));
            lv.x = ((uint32_t)__bfloat16_as_ushort(l1) << 16) | __bfloat16_as_ushort(l0);
            lv.y = ((uint32_t)__bfloat16_as_ushort(l3) << 16) | __bfloat16_as_ushort(l2);
            *(uint2*)&aH[r * SA + c4] = hv;
            *(uint2*)&aL[r * SA + c4] = lv;
        }
        // ---- issue B(c+1) into other buffer ----
        if (c < 7) {
            const int k0n = (c + 1) * 64;
            const uint32_t bo2 = (uint32_t)((c + 1) & 1) * BOFF;
#pragma unroll
            for (int p = 0; p < 4; p++) {
                int r = p * 32 + brr;
                size_t gv = (size_t)r * DIM + k0n + bu * 8;
                uint32_t so = (uint32_t)(r * SA + bu * 8) * 2;
                cp16(bBs + bo2 + so, g_vhi + gv);
                cp16(bBs + bo2 + BBUF * 2 + so, g_vlo + gv);
            }
            asm volatile("cp.async.commit_group;" ::: "memory");
            asm volatile("cp.async.wait_group 1;" ::: "memory");
        } else {
            asm volatile("cp.async.wait_group 0;" ::: "memory");
        }
        __syncthreads();

        // ---- prefetch A(c+1) regs (overlaps with MMA below) ----
        if (c < 7) {
            const int k0n = (c + 1) * 64;
#pragma unroll
            for (int p = 0; p < 4; p++) {
                int li = tid + p * 256;
                int r  = li >> 4;
                int c4 = (li & 15) * 4;
                xr[p] = *(const float4*)(x + (size_t)(bm + r) * DIM + k0n + c4);
            }
        }

        // ---- MMA over buffer (c&1) ----
#pragma unroll
        for (int kt = 0; kt < 4; kt++) {
            uint32_t ah[4], al[4];
            LDSM4(ah, aAdH + kt * 32);
            LDSM4(al, aAdL + kt * 32);
#pragma unroll
            for (int j = 0; j < 4; j++) {
                uint32_t bh[4], bl[4];
                LDSM4(bh, bAdH[j] + boff + kt * 32);
                LDSM4(bl, bAdL[j] + boff + kt * 32);
                mma_bf16(acc[2 * j],     ah, bh[0], bh[1]);
                mma_bf16(acc[2 * j],     ah, bl[0], bl[1]);
                mma_bf16(acc[2 * j],     al, bh[0], bh[1]);
                mma_bf16(acc[2 * j + 1], ah, bh[2], bh[3]);
                mma_bf16(acc[2 * j + 1], ah, bl[2], bl[3]);
                mma_bf16(acc[2 * j + 1], al, bh[2], bh[3]);
            }
        }
        __syncthreads();
    }

    // ---- epilogue ----
    float sv[2] = {0.f, 0.f}, dv[2] = {0.f, 0.f};
    const int row0 = bm + rb + g;
#pragma unroll
    for (int nt = 0; nt < 8; nt++) {
        int cb = n0 + nt * 8 + tig * 2;
        float2 bb = *(const float2*)&b[cb];
        float2 as = *(const float2*)&att[cb];
        float2 ad = *(const float2*)&att[FEAT + cb];
        float z0 = acc[nt][0] + bb.x;
        float z1 = acc[nt][1] + bb.y;
        float z2 = acc[nt][2] + bb.x;
        float z3 = acc[nt][3] + bb.y;
        *(float2*)&g_z[(size_t)row0 * FEAT + cb]       = make_float2(z0, z1);
        *(float2*)&g_z[(size_t)(row0 + 8) * FEAT + cb] = make_float2(z2, z3);
        sv[0] += z0 * as.x + z1 * as.y;
        sv[1] += z2 * as.x + z3 * as.y;
        dv[0] += z0 * ad.x + z1 * ad.y;
        dv[1] += z2 * ad.x + z3 * ad.y;
    }
#pragma unroll
    for (int h = 0; h < 2; h++) {
        sv[h] += __shfl_xor_sync(0xffffffffu, sv[h], 1);
        sv[h] += __shfl_xor_sync(0xffffffffu, sv[h], 2);
        dv[h] += __shfl_xor_sync(0xffffffffu, dv[h], 1);
        dv[h] += __shfl_xor_sync(0xffffffffu, dv[h], 2);
    }
    if (tig == 0) {
        int rl0 = rb + g;
        sdp[(nw * 64 + rl0) * 2 + 0]     = sv[0];
        sdp[(nw * 64 + rl0) * 2 + 1]     = dv[0];
        sdp[(nw * 64 + rl0 + 8) * 2 + 0] = sv[1];
        sdp[(nw * 64 + rl0 + 8) * 2 + 1] = dv[1];
    }
    __syncthreads();
    if (tid < 64) {
        float s = sdp[tid * 2]     + sdp[(64 + tid) * 2];
        float d = sdp[tid * 2 + 1] + sdp[(64 + tid) * 2 + 1];
        int row = bm + tid;
        g_s[row] = s;
        g_d[row] = d;
        unsigned int key = float_key(d);
        g_dkey[row] = ((unsigned long long)key << 32) | (unsigned int)row;
        unsigned int kmn = key, kmx = key;
#pragma unroll
        for (int off = 16; off; off >>= 1) {
            kmn = min(kmn, __shfl_xor_sync(0xffffffffu, kmn, off));
            kmx = max(kmx, __shfl_xor_sync(0xffffffffu, kmx, off));
        }
        if (lane == 0) {
            atomicMin(&g_kmin, kmn);
            atomicMax(&g_kmax, kmx);
        }
    }
}

// ---------------- 3) fused sort: hist -> scan -> place -> rank ---------------
__global__ void __launch_bounds__(256) sort_kernel() {
    const int nb  = 48;
    const int tid = threadIdx.x;
    const int bid = blockIdx.x;
    const int i   = bid * 256 + tid;

    unsigned long long kj = g_dkey[i];
    unsigned int key  = (unsigned int)(kj >> 32);
    unsigned int kmin = g_kmin;
    unsigned long long range = (unsigned long long)(g_kmax - kmin) + 1ull;
    int bin = (int)(((unsigned long long)(key - kmin) * NBUK) / range);
    g_bin[i] = bin;
    atomicAdd(&g_hist[bin], 1);
    grid_barrier(nb, &g_cnt1, &g_gen1);

    if (bid == 0) {
        __shared__ int ws[8];
        int base = tid * 16;
        int loc[16];
        int s = 0;
#pragma unroll
        for (int q = 0; q < 16; q++) { loc[q] = g_hist[base + q]; s += loc[q]; }
        int lane = tid & 31, wid = tid >> 5;
        int sc = s;
#pragma unroll
        for (int off = 1; off < 32; off <<= 1) {
            int o = __shfl_up_sync(0xffffffffu, sc, off);
            if (lane >= off) sc += o;
        }
        if (lane == 31) ws[wid] = sc;
        __syncthreads();
        if (tid == 0) {
            int run = 0;
#pragma unroll
            for (int q = 0; q < 8; q++) { int t2 = ws[q]; ws[q] = run; run += t2; }
        }
        __syncthreads();
        int run = ws[wid] + sc - s;
#pragma unroll
        for (int q = 0; q < 16; q++) { g_hstart[base + q] = run; run += loc[q]; }
    }
    grid_barrier(nb, &g_cnt1, &g_gen1);

    int pos = atomicAdd(&g_hcur[bin], 1);
    g_bkeys[g_hstart[bin] + pos] = kj;
    grid_barrier(nb, &g_cnt1, &g_gen1);

    int st  = g_hstart[bin];
    int cnt = g_hist[bin];
    int c = 0;
    for (int q = 0; q < cnt; q++) c += (g_bkeys[st + q] < kj) ? 1 : 0;
    int r = st + c;
    float d = g_d[i];
    g_inv[r]     = i;
    g_sortedD[r] = d;
    g_expD[r]    = expf(d);
}

// ---------------- 4) fused scans: MLP-batched local + parallel totals --------
__global__ void __launch_bounds__(256) scanAB_kernel() {
    int b    = blockIdx.x;
    int tid  = threadIdx.x;
    int base = b * TR;
    __shared__ int   jidx[TR];
    __shared__ float ed[TR];
    if (tid < TR) {
        jidx[tid] = g_inv[base + tid];
        ed[tid]   = g_expD[base + tid];
    }
    __syncthreads();

    if (tid < 128) {
        int f = tid;
        float acc = 0.f;
#pragma unroll
        for (int bt = 0; bt < 4; bt++) {
            float vals[16];
#pragma unroll
            for (int q = 0; q < 16; q++)
                vals[q] = g_z[(size_t)jidx[bt * 16 + q] * FEAT + f];
#pragma unroll
            for (int q = 0; q < 16; q++) {
                g_S0[(size_t)(base + bt * 16 + q) * FEAT + f] = acc;
                acc += vals[q];
            }
        }
        g_T0[b * FEAT + f] = acc;

        if (f < 32) {
            float v0 = ed[2 * f], v1 = ed[2 * f + 1];
            float seg = v0 + v1;
            float suf = seg;
#pragma unroll
            for (int off = 1; off < 32; off <<= 1) {
                float t2 = __shfl_down_sync(0xffffffffu, suf, off);
                if (f + off < 32) suf += t2;
            }
            float excl = suf - seg;
            g_c1[base + 2 * f + 1] = excl + v1;
            g_c1[base + 2 * f]     = excl + v1 + v0;
            if (f == 0) g_Tc[b] = suf;
        }
    } else {
        int f = tid - 128;
        float accS = 0.f;
#pragma unroll
        for (int bt = 3; bt >= 0; bt--) {
            float vals[16];
#pragma unroll
            for (int q = 0; q < 16; q++)
                vals[q] = ed[bt * 16 + q] * g_z[(size_t)jidx[bt * 16 + q] * FEAT + f];
#pragma unroll
            for (int q = 15; q >= 0; q--) {
                accS += vals[q];
                g_SufE[(size_t)(base + bt * 16 + q) * FEAT + f] = accS;
            }
        }
        g_TS[b * FEAT + f] = accS;
    }

    grid_barrier(NBR, &g_cnt2, &g_gen2);

    if (b < 128) {
        int f = b;
        bool act = tid < NBR;
        float v0 = act ? g_T0[tid * FEAT + f] : 0.f;
        float vS = act ? g_TS[tid * FEAT + f] : 0.f;
        float i0 = v0, iS = vS;
        int lane = tid & 31, wid = tid >> 5;
#pragma unroll
        for (int off = 1; off < 32; off <<= 1) {
            float a0 = __shfl_up_sync(0xffffffffu, i0, off);
            float aS = __shfl_up_sync(0xffffffffu, iS, off);
            if (lane >= off) { i0 += a0; iS += aS; }
        }
        __shared__ float w0[8], wS[8];
        __shared__ float tot0s, totSs;
        if (lane == 31) { w0[wid] = i0; wS[wid] = iS; }
        __syncthreads();
        if (tid == 0) {
            float r0 = 0.f, rS = 0.f;
#pragma unroll
            for (int q = 0; q < 8; q++) {
                float t0 = w0[q], tS = wS[q];
                w0[q] = r0; wS[q] = rS;
                r0 += t0; rS += tS;
            }
            tot0s = r0; totSs = rS;
        }
        __syncthreads();
        i0 += w0[wid];
        iS += wS[wid];
        if (act) {
            g_off0[tid * FEAT + f] = i0 - v0;
            g_offS[tid * FEAT + f] = totSs - iS;
        }
        if (tid == 0) {
            g_off0[NBR * FEAT + f] = tot0s;
            g_offS[NBR * FEAT + f] = 0.f;
            g_S0[(size_t)NROW * FEAT + f]   = 0.f;
            g_SufE[(size_t)NROW * FEAT + f] = 0.f;
        }
    } else if (b == 128) {
        bool act = tid < NBR;
        float vc = act ? g_Tc[tid] : 0.f;
        float ic = vc;
        int lane = tid & 31, wid = tid >> 5;
#pragma unroll
        for (int off = 1; off < 32; off <<= 1) {
            float a = __shfl_up_sync(0xffffffffu, ic, off);
            if (lane >= off) ic += a;
        }
        __shared__ float wc[8];
        __shared__ float totc;
        if (lane == 31) wc[wid] = ic;
        __syncthreads();
        if (tid == 0) {
            float r = 0.f;
#pragma unroll
            for (int q = 0; q < 8; q++) { float t2 = wc[q]; wc[q] = r; r += t2; }
            totc = r;
        }
        __syncthreads();
        ic += wc[wid];
        if (act) g_offc[tid] = totc - ic;
        if (tid == 0) { g_offc[NBR] = 0.f; g_c1[NROW] = 0.f; }
    }
}

// ---------------- 5) combine: warp-cooperative 32-ary search + softmax -------
__global__ void __launch_bounds__(128) combine_kernel(float* __restrict__ out) {
    int w    = threadIdx.x >> 5;
    int lane = threadIdx.x & 31;
    int i    = blockIdx.x * 4 + w;
    int f4   = lane * 4;

    float s = g_s[i];
    float thr = -s;

    // warp-cooperative 32-ary search for k = #{d <= thr}
    int lo = 0, hi = NROW;
#pragma unroll 1
    while (hi - lo > 32) {
        int len  = hi - lo;
        int step = (len + 31) >> 5;
        int p    = lo + (lane + 1) * step;          // test: k >= p  <=>  d[p-1] <= thr
        bool t = false;
        if (p - 1 < hi) t = (g_sortedD[p - 1] <= thr);
        unsigned bal = __ballot_sync(0xffffffffu, t);
        int cnt = __popc(bal);
        lo = lo + cnt * step;
        hi = min(hi, lo + step);
    }
    {
        int len = hi - lo;
        bool t = (lane < len) ? (g_sortedD[lo + lane] <= thr) : false;
        unsigned bal = __ballot_sync(0xffffffffu, t);
        lo += __popc(bal);
    }
    int k   = lo;
    int blk = k >> 6;

    float dmax  = g_sortedD[NROW - 1];
    float m     = fmaxf(0.f, s + dmax);
    float alpha = expf(s - m);
    float beta  = expf(-m);
    float den   = alpha * (g_offc[blk] + g_c1[k]) + beta * (float)k;
    float rden  = 1.f / den;

    float4 SufE = *(const float4*)&g_SufE[(size_t)k * FEAT + f4];
    float4 S0   = *(const float4*)&g_S0[(size_t)k * FEAT + f4];
    float4 offS = *(const float4*)&g_offS[(size_t)blk * FEAT + f4];
    float4 off0 = *(const float4*)&g_off0[(size_t)blk * FEAT + f4];
    float4 zv   = *(const float4*)&g_z[(size_t)i * FEAT + f4];

    float z2[4];
    z2[0] = (alpha * (offS.x + SufE.x) + beta * (off0.x + S0.x)) * rden + zv.x;
    z2[1] = (alpha * (offS.y + SufE.y) + beta * (off0.y + S0.y)) * rden + zv.y;
    z2[2] = (alpha * (offS.z + SufE.z) + beta * (off0.z + S0.z)) * rden + zv.z;
    z2[3] = (alpha * (offS.w + SufE.w) + beta * (off0.w + S0.w)) * rden + zv.w;

    float mx = fmaxf(fmaxf(z2[0], z2[1]), fmaxf(z2[2], z2[3]));
#pragma unroll
    for (int off = 16; off; off >>= 1) mx = fmaxf(mx, __shfl_xor_sync(0xffffffffu, mx, off));
    float e[4];
    float sm = 0.f;
#pragma unroll
    for (int q = 0; q < 4; q++) { e[q] = expf(z2[q] - mx); sm += e[q]; }
#pragma unroll
    for (int off = 16; off; off >>= 1) sm += __shfl_xor_sync(0xffffffffu, sm, off);
    float rs = 1.f / sm;
    float4 o = {e[0] * rs, e[1] * rs, e[2] * rs, e[3] * rs};
    *(float4*)&out[(size_t)i * FEAT + f4] = o;
}

// ---------------- launch ------------------------------------------------------
extern "C" void kernel_launch(void* const* d_in, const int* in_sizes, int n_in,
                              void* d_out, int out_size) {
    const float* x   = (const float*)d_in[0];   // [12288, 512]
    const float* v   = (const float*)d_in[1];   // [128, 512]
    const float* g   = (const float*)d_in[2];   // [128]
    const float* b   = (const float*)d_in[3];   // [128]
    const float* att = (const float*)d_in[4];   // [256]
    float* out = (float*)d_out;                 // [12288, 128]

    const int smem = (2 * ABUF + 4 * BBUF) * 2;   // 92160 bytes
    cudaFuncSetAttribute(gemm_mma_kernel, cudaFuncAttributeMaxDynamicSharedMemorySize, smem);

    prep_kernel<<<FEAT, 128>>>(v, g);
    gemm_mma_kernel<<<NROW / 64, 256, smem>>>(x, b, att);
    sort_kernel<<<48, 256>>>();
    scanAB_kernel<<<NBR, 256>>>();
    combine_kernel<<<NROW / 4, 128>>>(out);
}